// round 1
// baseline (speedup 1.0000x reference)
#include <cuda_runtime.h>

#define N_NODES 50000
#define N_EDGES 600000
#define DIM 128
#define OUTD 64

// ---- scratch (static device globals; no runtime allocation) ----
__device__ float g_y[N_NODES * 384];       // [m | gamma | beta] per node
__device__ float g_msg[N_NODES * DIM];     // FiLM messages per node
__device__ float g_h[N_NODES * DIM];       // normalized hidden state
__device__ int   g_deg[N_NODES];
__device__ int   g_off[N_NODES + 1];
__device__ int   g_cur[N_NODES];
__device__ int   g_csr_src[N_EDGES];

// ============================ CSR build ============================

__global__ void zero_deg_kernel() {
    int i = blockIdx.x * blockDim.x + threadIdx.x;
    if (i < N_NODES) g_deg[i] = 0;
}

__global__ void hist_kernel(const int* __restrict__ dst) {
    int e = blockIdx.x * blockDim.x + threadIdx.x;
    if (e < N_EDGES) atomicAdd(&g_deg[dst[e]], 1);
}

// single-block exclusive scan over g_deg -> g_off, g_cur
__global__ void scan_kernel() {
    __shared__ int wsum[32];
    int t = threadIdx.x;
    int lane = t & 31, wid = t >> 5;
    int carry = 0;
    for (int base = 0; base < N_NODES; base += 1024) {
        int idx = base + t;
        int v = (idx < N_NODES) ? g_deg[idx] : 0;
        int x = v;
#pragma unroll
        for (int o = 1; o < 32; o <<= 1) {
            int y = __shfl_up_sync(0xffffffffu, x, o);
            if (lane >= o) x += y;
        }
        if (lane == 31) wsum[wid] = x;
        __syncthreads();
        if (wid == 0) {
            int s = wsum[lane];
#pragma unroll
            for (int o = 1; o < 32; o <<= 1) {
                int y = __shfl_up_sync(0xffffffffu, s, o);
                if (lane >= o) s += y;
            }
            wsum[lane] = s;
        }
        __syncthreads();
        int wbase = (wid > 0) ? wsum[wid - 1] : 0;
        int excl = carry + wbase + x - v;
        if (idx < N_NODES) { g_off[idx] = excl; g_cur[idx] = excl; }
        carry += wsum[31];
        __syncthreads();
    }
    if (t == 0) g_off[N_NODES] = carry;
}

__global__ void fill_csr_kernel(const int* __restrict__ src, const int* __restrict__ dst) {
    int e = blockIdx.x * blockDim.x + threadIdx.x;
    if (e < N_EDGES) {
        int d = dst[e];
        int p = atomicAdd(&g_cur[d], 1);
        g_csr_src[p] = src[e];
    }
}

// ============================ GEMMs ============================
// Y[m,c] = sum_k A[m,k] * Wcat[c,k], Wcat = [W(128 rows); F(256 rows)], c in [0,384)
// Tiles: BM=64, BN=64, BK=16; 256 threads; 4x4 per thread.

__global__ void gemm_film384(const float* __restrict__ Ain,
                             const float* __restrict__ W,
                             const float* __restrict__ F,
                             int use_gh) {
    __shared__ float As[16][68];
    __shared__ float Bs[16][68];
    const float* A = use_gh ? g_h : Ain;

    int tid = threadIdx.x;
    int tx = tid & 15, ty = tid >> 4;
    int row0 = blockIdx.x * 64;
    int col0 = blockIdx.y * 64;

    float acc[4][4] = {};

    int lrow = tid >> 2;        // 0..63
    int lk4  = (tid & 3) * 4;   // 0,4,8,12

    int c = col0 + lrow;
    const float* bsrc = (c < 128) ? (W + c * 128) : (F + (c - 128) * 128);

    int arow = row0 + lrow;
    bool avalid = arow < N_NODES;
    const float* asrc = A + (avalid ? arow : 0) * 128;

    for (int kk = 0; kk < 128; kk += 16) {
        float4 av = avalid ? *(const float4*)(asrc + kk + lk4) : make_float4(0.f, 0.f, 0.f, 0.f);
        float4 bv = *(const float4*)(bsrc + kk + lk4);
        As[lk4 + 0][lrow] = av.x; As[lk4 + 1][lrow] = av.y;
        As[lk4 + 2][lrow] = av.z; As[lk4 + 3][lrow] = av.w;
        Bs[lk4 + 0][lrow] = bv.x; Bs[lk4 + 1][lrow] = bv.y;
        Bs[lk4 + 2][lrow] = bv.z; Bs[lk4 + 3][lrow] = bv.w;
        __syncthreads();
#pragma unroll
        for (int k = 0; k < 16; k++) {
            float4 a = *(const float4*)&As[k][ty * 4];
            float4 b = *(const float4*)&Bs[k][tx * 4];
            float aa[4] = {a.x, a.y, a.z, a.w};
            float bb[4] = {b.x, b.y, b.z, b.w};
#pragma unroll
            for (int i = 0; i < 4; i++)
#pragma unroll
                for (int j = 0; j < 4; j++)
                    acc[i][j] += aa[i] * bb[j];
        }
        __syncthreads();
    }
#pragma unroll
    for (int i = 0; i < 4; i++) {
        int r = row0 + ty * 4 + i;
        if (r < N_NODES) {
            float4 o = make_float4(acc[i][0], acc[i][1], acc[i][2], acc[i][3]);
            *(float4*)&g_y[r * 384 + col0 + tx * 4] = o;
        }
    }
}

// out = sigmoid(g_h @ Wp.T + bp), OUTD=64
__global__ void gemm_out(const float* __restrict__ Wp,
                         const float* __restrict__ bp,
                         float* __restrict__ out) {
    __shared__ float As[16][68];
    __shared__ float Bs[16][68];
    int tid = threadIdx.x;
    int tx = tid & 15, ty = tid >> 4;
    int row0 = blockIdx.x * 64;

    float acc[4][4] = {};

    int lrow = tid >> 2;
    int lk4  = (tid & 3) * 4;
    const float* bsrc = Wp + lrow * 128;  // lrow < 64 rows of Wp

    int arow = row0 + lrow;
    bool avalid = arow < N_NODES;
    const float* asrc = g_h + (avalid ? arow : 0) * 128;

    for (int kk = 0; kk < 128; kk += 16) {
        float4 av = avalid ? *(const float4*)(asrc + kk + lk4) : make_float4(0.f, 0.f, 0.f, 0.f);
        float4 bv = *(const float4*)(bsrc + kk + lk4);
        As[lk4 + 0][lrow] = av.x; As[lk4 + 1][lrow] = av.y;
        As[lk4 + 2][lrow] = av.z; As[lk4 + 3][lrow] = av.w;
        Bs[lk4 + 0][lrow] = bv.x; Bs[lk4 + 1][lrow] = bv.y;
        Bs[lk4 + 2][lrow] = bv.z; Bs[lk4 + 3][lrow] = bv.w;
        __syncthreads();
#pragma unroll
        for (int k = 0; k < 16; k++) {
            float4 a = *(const float4*)&As[k][ty * 4];
            float4 b = *(const float4*)&Bs[k][tx * 4];
            float aa[4] = {a.x, a.y, a.z, a.w};
            float bb[4] = {b.x, b.y, b.z, b.w};
#pragma unroll
            for (int i = 0; i < 4; i++)
#pragma unroll
                for (int j = 0; j < 4; j++)
                    acc[i][j] += aa[i] * bb[j];
        }
        __syncthreads();
    }
#pragma unroll
    for (int i = 0; i < 4; i++) {
        int r = row0 + ty * 4 + i;
        if (r < N_NODES) {
            float4 o;
            float v0 = acc[i][0] + bp[tx * 4 + 0];
            float v1 = acc[i][1] + bp[tx * 4 + 1];
            float v2 = acc[i][2] + bp[tx * 4 + 2];
            float v3 = acc[i][3] + bp[tx * 4 + 3];
            o.x = 1.f / (1.f + __expf(-v0));
            o.y = 1.f / (1.f + __expf(-v1));
            o.z = 1.f / (1.f + __expf(-v2));
            o.w = 1.f / (1.f + __expf(-v3));
            *(float4*)&out[r * 64 + tx * 4] = o;
        }
    }
}

// ============================ FiLM gate ============================
// msg = relu(gamma * m + beta); y row = [m(128) | gamma(128) | beta(128)]
__global__ void film_msg_kernel() {
    int idx = blockIdx.x * blockDim.x + threadIdx.x; // over N*32 float4 groups
    if (idx < N_NODES * 32) {
        int row = idx >> 5, cc = idx & 31;
        const float4* y4 = (const float4*)g_y;
        float4 m  = y4[row * 96 + cc];
        float4 ga = y4[row * 96 + 32 + cc];
        float4 be = y4[row * 96 + 64 + cc];
        float4 o;
        o.x = fmaxf(fmaf(ga.x, m.x, be.x), 0.f);
        o.y = fmaxf(fmaf(ga.y, m.y, be.y), 0.f);
        o.z = fmaxf(fmaf(ga.z, m.z, be.z), 0.f);
        o.w = fmaxf(fmaf(ga.w, m.w, be.w), 0.f);
        ((float4*)g_msg)[idx] = o;
    }
}

// ============================ aggregate + layernorm ============================
// warp per node: h[node] = sum over incoming edges of msg[src]; then LN fused.
__global__ void aggregate_ln_kernel(const float* __restrict__ gam,
                                    const float* __restrict__ bet) {
    int gw = (blockIdx.x * blockDim.x + threadIdx.x) >> 5;
    int lane = threadIdx.x & 31;
    if (gw >= N_NODES) return;

    int s0 = g_off[gw], s1 = g_off[gw + 1];
    const float4* msg4 = (const float4*)g_msg;

    float4 acc = make_float4(0.f, 0.f, 0.f, 0.f);
    for (int i = s0; i < s1; i++) {
        int s = __ldg(&g_csr_src[i]);
        float4 v = __ldg(&msg4[s * 32 + lane]);
        acc.x += v.x; acc.y += v.y; acc.z += v.z; acc.w += v.w;
    }

    float sum = acc.x + acc.y + acc.z + acc.w;
    float sq  = acc.x * acc.x + acc.y * acc.y + acc.z * acc.z + acc.w * acc.w;
#pragma unroll
    for (int o = 16; o > 0; o >>= 1) {
        sum += __shfl_xor_sync(0xffffffffu, sum, o);
        sq  += __shfl_xor_sync(0xffffffffu, sq,  o);
    }
    float mu  = sum * (1.f / 128.f);
    float var = sq * (1.f / 128.f) - mu * mu;
    float rs  = rsqrtf(var + 1e-5f);

    float4 gv = *(const float4*)&gam[lane * 4];
    float4 bv = *(const float4*)&bet[lane * 4];
    float4 o;
    o.x = (acc.x - mu) * rs * gv.x + bv.x;
    o.y = (acc.y - mu) * rs * gv.y + bv.y;
    o.z = (acc.z - mu) * rs * gv.z + bv.z;
    o.w = (acc.w - mu) * rs * gv.w + bv.w;
    *(float4*)&g_h[gw * 128 + lane * 4] = o;
}

// ============================ launch ============================

extern "C" void kernel_launch(void* const* d_in, const int* in_sizes, int n_in,
                              void* d_out, int out_size) {
    const float* features = (const float*)d_in[0];
    const int*   src      = (const int*)  d_in[1];
    const int*   dst      = (const int*)  d_in[2];
    const float* W1       = (const float*)d_in[3];
    const float* F1       = (const float*)d_in[4];
    const float* g1       = (const float*)d_in[5];
    const float* b1       = (const float*)d_in[6];
    const float* W2       = (const float*)d_in[7];
    const float* F2       = (const float*)d_in[8];
    const float* g2       = (const float*)d_in[9];
    const float* b2       = (const float*)d_in[10];
    const float* Wp       = (const float*)d_in[11];
    const float* bp       = (const float*)d_in[12];
    float* out = (float*)d_out;

    // CSR build (graph fixed across both layers)
    zero_deg_kernel<<<(N_NODES + 255) / 256, 256>>>();
    hist_kernel<<<(N_EDGES + 255) / 256, 256>>>(dst);
    scan_kernel<<<1, 1024>>>();
    fill_csr_kernel<<<(N_EDGES + 255) / 256, 256>>>(src, dst);

    dim3 gemm_grid((N_NODES + 63) / 64, 6);
    dim3 film_grid((N_NODES * 32 + 255) / 256);
    dim3 agg_grid((N_NODES + 7) / 8);   // 8 warps/block, warp per node

    // layer 1
    gemm_film384<<<gemm_grid, 256>>>(features, W1, F1, 0);
    film_msg_kernel<<<film_grid, 256>>>();
    aggregate_ln_kernel<<<agg_grid, 256>>>(g1, b1);

    // layer 2
    gemm_film384<<<gemm_grid, 256>>>(nullptr, W2, F2, 1);
    film_msg_kernel<<<film_grid, 256>>>();
    aggregate_ln_kernel<<<agg_grid, 256>>>(g2, b2);

    // output head
    gemm_out<<<(N_NODES + 63) / 64, 256>>>(Wp, bp, out);
}

// round 2
// speedup vs baseline: 1.5502x; 1.5502x over previous
#include <cuda_runtime.h>

#define N_NODES 50000
#define N_EDGES 600000
#define DIM 128
#define OUTD 64

#define PADA 132   // words per row for A/Wp tiles (k-stride)
#define PADB 68    // words per row for B 64-k chunks

// ---- scratch (static device globals; no runtime allocation) ----
__device__ float g_msg[N_NODES * DIM];     // FiLM messages per node
__device__ float g_h[N_NODES * DIM];       // normalized hidden state
__device__ int   g_deg[N_NODES];
__device__ int   g_off[N_NODES + 1];
__device__ int   g_cur[N_NODES];
__device__ int   g_csr_src[N_EDGES];

// ============================ helpers ============================

__device__ __forceinline__ unsigned f2tf32(float f) {
    unsigned u;
    asm("cvt.rna.tf32.f32 %0, %1;" : "=r"(u) : "f"(f));
    return u;
}

__device__ __forceinline__ void mma_tf32(float* c,
                                         unsigned a0, unsigned a1, unsigned a2, unsigned a3,
                                         unsigned b0, unsigned b1) {
    asm volatile(
        "mma.sync.aligned.m16n8k8.row.col.f32.tf32.tf32.f32 "
        "{%0,%1,%2,%3}, {%4,%5,%6,%7}, {%8,%9}, {%0,%1,%2,%3};"
        : "+f"(c[0]), "+f"(c[1]), "+f"(c[2]), "+f"(c[3])
        : "r"(a0), "r"(a1), "r"(a2), "r"(a3), "r"(b0), "r"(b1));
}

// ============================ CSR build ============================

__global__ void zero_deg_kernel() {
    int i = blockIdx.x * blockDim.x + threadIdx.x;
    if (i < N_NODES) g_deg[i] = 0;
}

__global__ void hist_kernel(const int* __restrict__ dst) {
    int e = blockIdx.x * blockDim.x + threadIdx.x;
    if (e < N_EDGES) atomicAdd(&g_deg[dst[e]], 1);
}

__global__ void scan_kernel() {
    __shared__ int wsum[32];
    int t = threadIdx.x;
    int lane = t & 31, wid = t >> 5;
    int carry = 0;
    for (int base = 0; base < N_NODES; base += 1024) {
        int idx = base + t;
        int v = (idx < N_NODES) ? g_deg[idx] : 0;
        int x = v;
#pragma unroll
        for (int o = 1; o < 32; o <<= 1) {
            int y = __shfl_up_sync(0xffffffffu, x, o);
            if (lane >= o) x += y;
        }
        if (lane == 31) wsum[wid] = x;
        __syncthreads();
        if (wid == 0) {
            int s = wsum[lane];
#pragma unroll
            for (int o = 1; o < 32; o <<= 1) {
                int y = __shfl_up_sync(0xffffffffu, s, o);
                if (lane >= o) s += y;
            }
            wsum[lane] = s;
        }
        __syncthreads();
        int wbase = (wid > 0) ? wsum[wid - 1] : 0;
        int excl = carry + wbase + x - v;
        if (idx < N_NODES) { g_off[idx] = excl; g_cur[idx] = excl; }
        carry += wsum[31];
        __syncthreads();
    }
    if (t == 0) g_off[N_NODES] = carry;
}

__global__ void fill_csr_kernel(const int* __restrict__ src, const int* __restrict__ dst) {
    int e = blockIdx.x * blockDim.x + threadIdx.x;
    if (e < N_EDGES) {
        int d = dst[e];
        int p = atomicAdd(&g_cur[d], 1);
        g_csr_src[p] = src[e];
    }
}

// ==================== fused FiLM GEMM (tf32 tensor cores) ====================
// Per block: 64 node rows. For j in {0,1} (two 64-col halves of the 128 msg cols):
//   compute m (W rows 64j..), gamma (F rows 64j..), beta (F rows 128+64j..)
//   as three 64x64 tf32 MMA tiles accumulated over K=128, then fuse
//   msg = relu(gamma*m + beta) in registers and store directly.
// smem: sA[64][PADA] (tf32 A tile, full K) + sB[192][PADB] (64-K chunk of 192 weight rows).

__global__ void film_gemm_fused(const float* __restrict__ Ain,
                                const float* __restrict__ W,
                                const float* __restrict__ F,
                                int use_gh) {
    extern __shared__ unsigned smem[];
    unsigned* sA = smem;                   // 64*PADA
    unsigned* sB = smem + 64 * PADA;       // 192*PADB

    const float* A = use_gh ? g_h : Ain;

    int tid  = threadIdx.x;
    int wid  = tid >> 5;
    int lane = tid & 31;
    int g    = lane >> 2;       // 0..7
    int tg   = lane & 3;        // 0..3
    int wr   = wid >> 1;        // 0..3 (16-row group)
    int wc   = wid & 1;         // 0..1 (32-col group)
    int row0 = blockIdx.x * 64;

    // load A tile (64 rows x 128 K) as tf32
    for (int idx = tid; idx < 64 * 32; idx += 256) {
        int r = idx >> 5;
        int c4 = (idx & 31) * 4;
        int grow = row0 + r;
        float4 v = (grow < N_NODES) ? *(const float4*)(A + grow * 128 + c4)
                                    : make_float4(0.f, 0.f, 0.f, 0.f);
        unsigned* p = sA + r * PADA + c4;
        p[0] = f2tf32(v.x); p[1] = f2tf32(v.y); p[2] = f2tf32(v.z); p[3] = f2tf32(v.w);
    }

#pragma unroll
    for (int j = 0; j < 2; j++) {
        float acc[3][4][4];
#pragma unroll
        for (int m = 0; m < 3; m++)
#pragma unroll
            for (int n = 0; n < 4; n++)
#pragma unroll
                for (int q = 0; q < 4; q++) acc[m][n][q] = 0.f;

#pragma unroll
        for (int kc = 0; kc < 2; kc++) {
            int kb = kc * 64;
            __syncthreads();
            // load 192 weight rows x 64 K-chunk
            for (int idx = tid; idx < 192 * 16; idx += 256) {
                int r = idx >> 4;
                int c4 = (idx & 15) * 4;
                const float* srcRow;
                if (r < 64)       srcRow = W + (64 * j + r) * 128;        // m
                else if (r < 128) srcRow = F + (64 * j + r - 64) * 128;   // gamma
                else              srcRow = F + (64 * j + r) * 128;        // beta (128+64j+(r-128))
                float4 v = *(const float4*)(srcRow + kb + c4);
                unsigned* p = sB + r * PADB + c4;
                p[0] = f2tf32(v.x); p[1] = f2tf32(v.y); p[2] = f2tf32(v.z); p[3] = f2tf32(v.w);
            }
            __syncthreads();

            const unsigned* aW = sA + (wr * 16 + g) * PADA + kb + tg;
#pragma unroll
            for (int ks = 0; ks < 8; ks++) {
                int k0 = ks * 8;
                unsigned a0 = aW[k0];
                unsigned a1 = aW[8 * PADA + k0];
                unsigned a2 = aW[k0 + 4];
                unsigned a3 = aW[8 * PADA + k0 + 4];
#pragma unroll
                for (int mat = 0; mat < 3; mat++) {
#pragma unroll
                    for (int nt = 0; nt < 4; nt++) {
                        const unsigned* bptr = sB + (mat * 64 + wc * 32 + nt * 8 + g) * PADB + k0 + tg;
                        unsigned b0 = bptr[0];
                        unsigned b1 = bptr[4];
                        mma_tf32(acc[mat][nt], a0, a1, a2, a3, b0, b1);
                    }
                }
            }
        }

        // epilogue: msg = relu(gamma*m + beta), cols [64j + wc*32, +32)
        int ra = row0 + wr * 16 + g;
        int rb = ra + 8;
#pragma unroll
        for (int nt = 0; nt < 4; nt++) {
            int col = 64 * j + wc * 32 + nt * 8 + 2 * tg;
            float v0 = fmaxf(fmaf(acc[1][nt][0], acc[0][nt][0], acc[2][nt][0]), 0.f);
            float v1 = fmaxf(fmaf(acc[1][nt][1], acc[0][nt][1], acc[2][nt][1]), 0.f);
            float v2 = fmaxf(fmaf(acc[1][nt][2], acc[0][nt][2], acc[2][nt][2]), 0.f);
            float v3 = fmaxf(fmaf(acc[1][nt][3], acc[0][nt][3], acc[2][nt][3]), 0.f);
            if (ra < N_NODES) *(float2*)&g_msg[ra * 128 + col] = make_float2(v0, v1);
            if (rb < N_NODES) *(float2*)&g_msg[rb * 128 + col] = make_float2(v2, v3);
        }
    }
}

// ==================== output head: sigmoid(g_h @ Wp.T + bp) ====================

__global__ void gemm_out_tc(const float* __restrict__ Wp,
                            const float* __restrict__ bp,
                            float* __restrict__ out) {
    extern __shared__ unsigned smem[];
    unsigned* sA = smem;                 // 64*PADA
    unsigned* sB = smem + 64 * PADA;     // 64*PADA (Wp, full K)

    int tid  = threadIdx.x;
    int wid  = tid >> 5;
    int lane = tid & 31;
    int g    = lane >> 2;
    int tg   = lane & 3;
    int wr   = wid >> 1;
    int wc   = wid & 1;
    int row0 = blockIdx.x * 64;

    for (int idx = tid; idx < 64 * 32; idx += 256) {
        int r = idx >> 5;
        int c4 = (idx & 31) * 4;
        int grow = row0 + r;
        float4 v = (grow < N_NODES) ? *(const float4*)(g_h + grow * 128 + c4)
                                    : make_float4(0.f, 0.f, 0.f, 0.f);
        unsigned* p = sA + r * PADA + c4;
        p[0] = f2tf32(v.x); p[1] = f2tf32(v.y); p[2] = f2tf32(v.z); p[3] = f2tf32(v.w);
    }
    for (int idx = tid; idx < 64 * 32; idx += 256) {
        int r = idx >> 5;
        int c4 = (idx & 31) * 4;
        float4 v = *(const float4*)(Wp + r * 128 + c4);
        unsigned* p = sB + r * PADA + c4;
        p[0] = f2tf32(v.x); p[1] = f2tf32(v.y); p[2] = f2tf32(v.z); p[3] = f2tf32(v.w);
    }
    __syncthreads();

    float acc[4][4];
#pragma unroll
    for (int n = 0; n < 4; n++)
#pragma unroll
        for (int q = 0; q < 4; q++) acc[n][q] = 0.f;

    const unsigned* aW = sA + (wr * 16 + g) * PADA + tg;
#pragma unroll
    for (int ks = 0; ks < 16; ks++) {
        int k0 = ks * 8;
        unsigned a0 = aW[k0];
        unsigned a1 = aW[8 * PADA + k0];
        unsigned a2 = aW[k0 + 4];
        unsigned a3 = aW[8 * PADA + k0 + 4];
#pragma unroll
        for (int nt = 0; nt < 4; nt++) {
            const unsigned* bptr = sB + (wc * 32 + nt * 8 + g) * PADA + k0 + tg;
            mma_tf32(acc[nt], a0, a1, a2, a3, bptr[0], bptr[4]);
        }
    }

    int ra = row0 + wr * 16 + g;
    int rb = ra + 8;
#pragma unroll
    for (int nt = 0; nt < 4; nt++) {
        int col = wc * 32 + nt * 8 + 2 * tg;
        float bpv0 = bp[col], bpv1 = bp[col + 1];
        float v0 = 1.f / (1.f + __expf(-(acc[nt][0] + bpv0)));
        float v1 = 1.f / (1.f + __expf(-(acc[nt][1] + bpv1)));
        float v2 = 1.f / (1.f + __expf(-(acc[nt][2] + bpv0)));
        float v3 = 1.f / (1.f + __expf(-(acc[nt][3] + bpv1)));
        if (ra < N_NODES) *(float2*)&out[ra * 64 + col] = make_float2(v0, v1);
        if (rb < N_NODES) *(float2*)&out[rb * 64 + col] = make_float2(v2, v3);
    }
}

// ==================== aggregate + layernorm (fused, warp per node) ====================

__global__ void aggregate_ln_kernel(const float* __restrict__ gam,
                                    const float* __restrict__ bet) {
    int gw = (blockIdx.x * blockDim.x + threadIdx.x) >> 5;
    int lane = threadIdx.x & 31;
    if (gw >= N_NODES) return;

    int s0 = g_off[gw], s1 = g_off[gw + 1];
    const float4* msg4 = (const float4*)g_msg;

    float4 acc = make_float4(0.f, 0.f, 0.f, 0.f);
    for (int i = s0; i < s1; i++) {
        int s = __ldg(&g_csr_src[i]);
        float4 v = __ldg(&msg4[s * 32 + lane]);
        acc.x += v.x; acc.y += v.y; acc.z += v.z; acc.w += v.w;
    }

    float sum = acc.x + acc.y + acc.z + acc.w;
    float sq  = acc.x * acc.x + acc.y * acc.y + acc.z * acc.z + acc.w * acc.w;
#pragma unroll
    for (int o = 16; o > 0; o >>= 1) {
        sum += __shfl_xor_sync(0xffffffffu, sum, o);
        sq  += __shfl_xor_sync(0xffffffffu, sq,  o);
    }
    float mu  = sum * (1.f / 128.f);
    float var = sq * (1.f / 128.f) - mu * mu;
    float rs  = rsqrtf(var + 1e-5f);

    float4 gv = *(const float4*)&gam[lane * 4];
    float4 bv = *(const float4*)&bet[lane * 4];
    float4 o;
    o.x = (acc.x - mu) * rs * gv.x + bv.x;
    o.y = (acc.y - mu) * rs * gv.y + bv.y;
    o.z = (acc.z - mu) * rs * gv.z + bv.z;
    o.w = (acc.w - mu) * rs * gv.w + bv.w;
    *(float4*)&g_h[gw * 128 + lane * 4] = o;
}

// ============================ launch ============================

extern "C" void kernel_launch(void* const* d_in, const int* in_sizes, int n_in,
                              void* d_out, int out_size) {
    const float* features = (const float*)d_in[0];
    const int*   src      = (const int*)  d_in[1];
    const int*   dst      = (const int*)  d_in[2];
    const float* W1       = (const float*)d_in[3];
    const float* F1       = (const float*)d_in[4];
    const float* g1       = (const float*)d_in[5];
    const float* b1       = (const float*)d_in[6];
    const float* W2       = (const float*)d_in[7];
    const float* F2       = (const float*)d_in[8];
    const float* g2       = (const float*)d_in[9];
    const float* b2       = (const float*)d_in[10];
    const float* Wp       = (const float*)d_in[11];
    const float* bp       = (const float*)d_in[12];
    float* out = (float*)d_out;

    const int smem_film = (64 * PADA + 192 * PADB) * 4;   // 86016 B
    const int smem_out  = (64 * PADA + 64 * PADA) * 4;    // 67584 B
    cudaFuncSetAttribute(film_gemm_fused, cudaFuncAttributeMaxDynamicSharedMemorySize, smem_film);
    cudaFuncSetAttribute(gemm_out_tc,     cudaFuncAttributeMaxDynamicSharedMemorySize, smem_out);

    // CSR build (graph fixed across both layers)
    zero_deg_kernel<<<(N_NODES + 255) / 256, 256>>>();
    hist_kernel<<<(N_EDGES + 255) / 256, 256>>>(dst);
    scan_kernel<<<1, 1024>>>();
    fill_csr_kernel<<<(N_EDGES + 255) / 256, 256>>>(src, dst);

    dim3 gemm_grid((N_NODES + 63) / 64);
    dim3 agg_grid((N_NODES + 7) / 8);   // 8 warps/block, warp per node

    // layer 1
    film_gemm_fused<<<gemm_grid, 256, smem_film>>>(features, W1, F1, 0);
    aggregate_ln_kernel<<<agg_grid, 256>>>(g1, b1);

    // layer 2
    film_gemm_fused<<<gemm_grid, 256, smem_film>>>(nullptr, W2, F2, 1);
    aggregate_ln_kernel<<<agg_grid, 256>>>(g2, b2);

    // output head
    gemm_out_tc<<<gemm_grid, 256, smem_out>>>(Wp, bp, out);
}

// round 3
// speedup vs baseline: 1.7792x; 1.1477x over previous
#include <cuda_runtime.h>

#define N_NODES 50000
#define N_EDGES 600000
#define DIM 128
#define OUTD 64

#define PADA 132   // words per row for A tiles (k-stride)
#define PADB 68    // words per row for B 64-k chunks

// ---- scratch (static device globals; no runtime allocation) ----
__device__ float    g_msg[N_NODES * DIM];
__device__ float    g_h[N_NODES * DIM];
__device__ int      g_deg[N_NODES];
__device__ int      g_off[N_NODES + 1];
__device__ int      g_cur[N_NODES];
__device__ int      g_csr_src[N_EDGES];
__device__ unsigned g_Bt1[2 * 192 * 128];   // layer-1 weights, tf32, usage order
__device__ unsigned g_Bt2[2 * 192 * 128];   // layer-2 weights
__device__ unsigned g_Bp[64 * 128];         // Wp, tf32

// ============================ helpers ============================

__device__ __forceinline__ unsigned f2tf32(float f) {
    unsigned u;
    asm("cvt.rna.tf32.f32 %0, %1;" : "=r"(u) : "f"(f));
    return u;
}

__device__ __forceinline__ void mma_tf32(float* c,
                                         unsigned a0, unsigned a1, unsigned a2, unsigned a3,
                                         unsigned b0, unsigned b1) {
    asm volatile(
        "mma.sync.aligned.m16n8k8.row.col.f32.tf32.tf32.f32 "
        "{%0,%1,%2,%3}, {%4,%5,%6,%7}, {%8,%9}, {%0,%1,%2,%3};"
        : "+f"(c[0]), "+f"(c[1]), "+f"(c[2]), "+f"(c[3])
        : "r"(a0), "r"(a1), "r"(a2), "r"(a3), "r"(b0), "r"(b1));
}

// ============================ CSR build ============================

__global__ void zero_deg_kernel() {
    int i = blockIdx.x * blockDim.x + threadIdx.x;
    if (i < N_NODES) g_deg[i] = 0;
}

__global__ void hist_kernel(const int* __restrict__ dst) {
    int e = blockIdx.x * blockDim.x + threadIdx.x;
    if (e < N_EDGES) atomicAdd(&g_deg[dst[e]], 1);
}

__global__ void scan_kernel() {
    __shared__ int wsum[32];
    int t = threadIdx.x;
    int lane = t & 31, wid = t >> 5;
    int carry = 0;
    for (int base = 0; base < N_NODES; base += 1024) {
        int idx = base + t;
        int v = (idx < N_NODES) ? g_deg[idx] : 0;
        int x = v;
#pragma unroll
        for (int o = 1; o < 32; o <<= 1) {
            int y = __shfl_up_sync(0xffffffffu, x, o);
            if (lane >= o) x += y;
        }
        if (lane == 31) wsum[wid] = x;
        __syncthreads();
        if (wid == 0) {
            int s = wsum[lane];
#pragma unroll
            for (int o = 1; o < 32; o <<= 1) {
                int y = __shfl_up_sync(0xffffffffu, s, o);
                if (lane >= o) s += y;
            }
            wsum[lane] = s;
        }
        __syncthreads();
        int wbase = (wid > 0) ? wsum[wid - 1] : 0;
        int excl = carry + wbase + x - v;
        if (idx < N_NODES) { g_off[idx] = excl; g_cur[idx] = excl; }
        carry += wsum[31];
        __syncthreads();
    }
    if (t == 0) g_off[N_NODES] = carry;
}

__global__ void fill_csr_kernel(const int* __restrict__ src, const int* __restrict__ dst) {
    int e = blockIdx.x * blockDim.x + threadIdx.x;
    if (e < N_EDGES) {
        int d = dst[e];
        int p = atomicAdd(&g_cur[d], 1);
        g_csr_src[p] = src[e];
    }
}

// ==================== weight pre-conversion (fp32 -> tf32, usage order) ====================
// g_Bt layout: [(j*192 + r)*128 + k], r<64: m rows W[64j+r]; r<128: gamma F[64j+r-64];
// r<192: beta F[64j+r] (r>=128 gives F rows 128+64j+(r-128)).

__global__ void prep_weights(const float* __restrict__ W,
                             const float* __restrict__ F,
                             int layer) {
    unsigned* dst = layer ? g_Bt2 : g_Bt1;
    int idx = blockIdx.x * blockDim.x + threadIdx.x;   // over 2*192*32 float4 groups
    if (idx >= 2 * 192 * 32) return;
    int j  = idx / (192 * 32);
    int r  = (idx >> 5) % 192;
    int c4 = (idx & 31) * 4;
    const float* srcRow;
    if (r < 64)       srcRow = W + (64 * j + r) * 128;
    else if (r < 128) srcRow = F + (64 * j + r - 64) * 128;
    else              srcRow = F + (64 * j + r) * 128;
    float4 v = *(const float4*)(srcRow + c4);
    unsigned* p = dst + idx * 4;
    p[0] = f2tf32(v.x); p[1] = f2tf32(v.y); p[2] = f2tf32(v.z); p[3] = f2tf32(v.w);
}

__global__ void prep_wp(const float* __restrict__ Wp) {
    int idx = blockIdx.x * blockDim.x + threadIdx.x;   // over 64*32 float4 groups
    if (idx >= 64 * 32) return;
    float4 v = *(const float4*)(Wp + idx * 4);
    unsigned* p = g_Bp + idx * 4;
    p[0] = f2tf32(v.x); p[1] = f2tf32(v.y); p[2] = f2tf32(v.z); p[3] = f2tf32(v.w);
}

// ==================== fused FiLM GEMM (tf32 tensor cores, M=128, 512 thr) ====================

__global__ void film_gemm_fused(const float* __restrict__ Ain, int layer) {
    extern __shared__ unsigned smem[];
    unsigned* sA = smem;                   // 128*PADA
    unsigned* sB = smem + 128 * PADA;      // 192*PADB

    const float*    A  = layer ? g_h : Ain;
    const unsigned* Bt = layer ? g_Bt2 : g_Bt1;

    int tid  = threadIdx.x;     // 512
    int wid  = tid >> 5;
    int lane = tid & 31;
    int g    = lane >> 2;       // 0..7
    int tg   = lane & 3;        // 0..3
    int wr   = wid >> 1;        // 0..7 (16-row group)
    int wc   = wid & 1;         // 0..1 (32-col group)
    int row0 = blockIdx.x * 128;

    // load A tile (128 rows x 128 K) as tf32
    for (int idx = tid; idx < 128 * 32; idx += 512) {
        int r = idx >> 5;
        int c4 = (idx & 31) * 4;
        int grow = row0 + r;
        float4 v = (grow < N_NODES) ? *(const float4*)(A + grow * 128 + c4)
                                    : make_float4(0.f, 0.f, 0.f, 0.f);
        unsigned* p = sA + r * PADA + c4;
        p[0] = f2tf32(v.x); p[1] = f2tf32(v.y); p[2] = f2tf32(v.z); p[3] = f2tf32(v.w);
    }

#pragma unroll
    for (int j = 0; j < 2; j++) {
        float acc[3][4][4];
#pragma unroll
        for (int m = 0; m < 3; m++)
#pragma unroll
            for (int n = 0; n < 4; n++)
#pragma unroll
                for (int q = 0; q < 4; q++) acc[m][n][q] = 0.f;

#pragma unroll
        for (int kc = 0; kc < 2; kc++) {
            int kb = kc * 64;
            __syncthreads();
            // copy 192 weight rows x 64 K-chunk (already tf32)
            for (int idx = tid; idx < 192 * 16; idx += 512) {
                int r = idx >> 4;
                int c4 = (idx & 15) * 4;
                uint4 v = *(const uint4*)(Bt + (j * 192 + r) * 128 + kb + c4);
                *(uint4*)(sB + r * PADB + c4) = v;
            }
            __syncthreads();

            const unsigned* aW = sA + (wr * 16 + g) * PADA + kb + tg;
#pragma unroll
            for (int ks = 0; ks < 8; ks++) {
                int k0 = ks * 8;
                unsigned a0 = aW[k0];
                unsigned a1 = aW[8 * PADA + k0];
                unsigned a2 = aW[k0 + 4];
                unsigned a3 = aW[8 * PADA + k0 + 4];
#pragma unroll
                for (int mat = 0; mat < 3; mat++) {
#pragma unroll
                    for (int nt = 0; nt < 4; nt++) {
                        const unsigned* bptr = sB + (mat * 64 + wc * 32 + nt * 8 + g) * PADB + k0 + tg;
                        mma_tf32(acc[mat][nt], a0, a1, a2, a3, bptr[0], bptr[4]);
                    }
                }
            }
        }

        // epilogue: msg = relu(gamma*m + beta)
        int ra = row0 + wr * 16 + g;
        int rb = ra + 8;
#pragma unroll
        for (int nt = 0; nt < 4; nt++) {
            int col = 64 * j + wc * 32 + nt * 8 + 2 * tg;
            float v0 = fmaxf(fmaf(acc[1][nt][0], acc[0][nt][0], acc[2][nt][0]), 0.f);
            float v1 = fmaxf(fmaf(acc[1][nt][1], acc[0][nt][1], acc[2][nt][1]), 0.f);
            float v2 = fmaxf(fmaf(acc[1][nt][2], acc[0][nt][2], acc[2][nt][2]), 0.f);
            float v3 = fmaxf(fmaf(acc[1][nt][3], acc[0][nt][3], acc[2][nt][3]), 0.f);
            if (ra < N_NODES) *(float2*)&g_msg[ra * 128 + col] = make_float2(v0, v1);
            if (rb < N_NODES) *(float2*)&g_msg[rb * 128 + col] = make_float2(v2, v3);
        }
    }
}

// ==================== output head: sigmoid(g_h @ Wp.T + bp) ====================

__global__ void gemm_out_tc(const float* __restrict__ bp,
                            float* __restrict__ out) {
    extern __shared__ unsigned smem[];
    unsigned* sA = smem;                 // 64*PADA
    unsigned* sB = smem + 64 * PADA;     // 64*PADA

    int tid  = threadIdx.x;
    int wid  = tid >> 5;
    int lane = tid & 31;
    int g    = lane >> 2;
    int tg   = lane & 3;
    int wr   = wid >> 1;
    int wc   = wid & 1;
    int row0 = blockIdx.x * 64;

    for (int idx = tid; idx < 64 * 32; idx += 256) {
        int r = idx >> 5;
        int c4 = (idx & 31) * 4;
        int grow = row0 + r;
        float4 v = (grow < N_NODES) ? *(const float4*)(g_h + grow * 128 + c4)
                                    : make_float4(0.f, 0.f, 0.f, 0.f);
        unsigned* p = sA + r * PADA + c4;
        p[0] = f2tf32(v.x); p[1] = f2tf32(v.y); p[2] = f2tf32(v.z); p[3] = f2tf32(v.w);
    }
    for (int idx = tid; idx < 64 * 32; idx += 256) {
        int r = idx >> 5;
        int c4 = (idx & 31) * 4;
        uint4 v = *(const uint4*)(g_Bp + r * 128 + c4);
        *(uint4*)(sB + r * PADA + c4) = v;
    }
    __syncthreads();

    float acc[4][4];
#pragma unroll
    for (int n = 0; n < 4; n++)
#pragma unroll
        for (int q = 0; q < 4; q++) acc[n][q] = 0.f;

    const unsigned* aW = sA + (wr * 16 + g) * PADA + tg;
#pragma unroll
    for (int ks = 0; ks < 16; ks++) {
        int k0 = ks * 8;
        unsigned a0 = aW[k0];
        unsigned a1 = aW[8 * PADA + k0];
        unsigned a2 = aW[k0 + 4];
        unsigned a3 = aW[8 * PADA + k0 + 4];
#pragma unroll
        for (int nt = 0; nt < 4; nt++) {
            const unsigned* bptr = sB + (wc * 32 + nt * 8 + g) * PADA + k0 + tg;
            mma_tf32(acc[nt], a0, a1, a2, a3, bptr[0], bptr[4]);
        }
    }

    int ra = row0 + wr * 16 + g;
    int rb = ra + 8;
#pragma unroll
    for (int nt = 0; nt < 4; nt++) {
        int col = wc * 32 + nt * 8 + 2 * tg;
        float bpv0 = bp[col], bpv1 = bp[col + 1];
        float v0 = 1.f / (1.f + __expf(-(acc[nt][0] + bpv0)));
        float v1 = 1.f / (1.f + __expf(-(acc[nt][1] + bpv1)));
        float v2 = 1.f / (1.f + __expf(-(acc[nt][2] + bpv0)));
        float v3 = 1.f / (1.f + __expf(-(acc[nt][3] + bpv1)));
        if (ra < N_NODES) *(float2*)&out[ra * 64 + col] = make_float2(v0, v1);
        if (rb < N_NODES) *(float2*)&out[rb * 64 + col] = make_float2(v2, v3);
    }
}

// ==================== aggregate + layernorm (fused, warp per node) ====================

__global__ void aggregate_ln_kernel(const float* __restrict__ gam,
                                    const float* __restrict__ bet) {
    int gw = (blockIdx.x * blockDim.x + threadIdx.x) >> 5;
    int lane = threadIdx.x & 31;
    if (gw >= N_NODES) return;

    int s0 = g_off[gw], s1 = g_off[gw + 1];
    const float4* msg4 = (const float4*)g_msg;

    float4 acc0 = make_float4(0.f, 0.f, 0.f, 0.f);
    float4 acc1 = make_float4(0.f, 0.f, 0.f, 0.f);
    int i = s0;
    for (; i + 2 <= s1; i += 2) {
        int sa = __ldg(&g_csr_src[i]);
        int sb = __ldg(&g_csr_src[i + 1]);
        float4 va = __ldg(&msg4[sa * 32 + lane]);
        float4 vb = __ldg(&msg4[sb * 32 + lane]);
        acc0.x += va.x; acc0.y += va.y; acc0.z += va.z; acc0.w += va.w;
        acc1.x += vb.x; acc1.y += vb.y; acc1.z += vb.z; acc1.w += vb.w;
    }
    if (i < s1) {
        int sa = __ldg(&g_csr_src[i]);
        float4 va = __ldg(&msg4[sa * 32 + lane]);
        acc0.x += va.x; acc0.y += va.y; acc0.z += va.z; acc0.w += va.w;
    }
    float4 acc = make_float4(acc0.x + acc1.x, acc0.y + acc1.y,
                             acc0.z + acc1.z, acc0.w + acc1.w);

    float sum = acc.x + acc.y + acc.z + acc.w;
    float sq  = acc.x * acc.x + acc.y * acc.y + acc.z * acc.z + acc.w * acc.w;
#pragma unroll
    for (int o = 16; o > 0; o >>= 1) {
        sum += __shfl_xor_sync(0xffffffffu, sum, o);
        sq  += __shfl_xor_sync(0xffffffffu, sq,  o);
    }
    float mu  = sum * (1.f / 128.f);
    float var = sq * (1.f / 128.f) - mu * mu;
    float rs  = rsqrtf(var + 1e-5f);

    float4 gv = *(const float4*)&gam[lane * 4];
    float4 bv = *(const float4*)&bet[lane * 4];
    float4 o;
    o.x = (acc.x - mu) * rs * gv.x + bv.x;
    o.y = (acc.y - mu) * rs * gv.y + bv.y;
    o.z = (acc.z - mu) * rs * gv.z + bv.z;
    o.w = (acc.w - mu) * rs * gv.w + bv.w;
    *(float4*)&g_h[gw * 128 + lane * 4] = o;
}

// ============================ launch ============================

extern "C" void kernel_launch(void* const* d_in, const int* in_sizes, int n_in,
                              void* d_out, int out_size) {
    const float* features = (const float*)d_in[0];
    const int*   src      = (const int*)  d_in[1];
    const int*   dst      = (const int*)  d_in[2];
    const float* W1       = (const float*)d_in[3];
    const float* F1       = (const float*)d_in[4];
    const float* g1       = (const float*)d_in[5];
    const float* b1       = (const float*)d_in[6];
    const float* W2       = (const float*)d_in[7];
    const float* F2       = (const float*)d_in[8];
    const float* g2       = (const float*)d_in[9];
    const float* b2       = (const float*)d_in[10];
    const float* Wp       = (const float*)d_in[11];
    const float* bp       = (const float*)d_in[12];
    float* out = (float*)d_out;

    const int smem_film = (128 * PADA + 192 * PADB) * 4;   // 119808 B
    const int smem_out  = (64 * PADA + 64 * PADA) * 4;     // 67584 B
    cudaFuncSetAttribute(film_gemm_fused, cudaFuncAttributeMaxDynamicSharedMemorySize, smem_film);
    cudaFuncSetAttribute(gemm_out_tc,     cudaFuncAttributeMaxDynamicSharedMemorySize, smem_out);

    // CSR build + weight prep
    zero_deg_kernel<<<(N_NODES + 255) / 256, 256>>>();
    hist_kernel<<<(N_EDGES + 255) / 256, 256>>>(dst);
    scan_kernel<<<1, 1024>>>();
    fill_csr_kernel<<<(N_EDGES + 255) / 256, 256>>>(src, dst);
    prep_weights<<<(2 * 192 * 32 + 255) / 256, 256>>>(W1, F1, 0);
    prep_weights<<<(2 * 192 * 32 + 255) / 256, 256>>>(W2, F2, 1);
    prep_wp<<<(64 * 32 + 255) / 256, 256>>>(Wp);

    dim3 film_grid((N_NODES + 127) / 128);
    dim3 agg_grid((N_NODES + 7) / 8);

    // layer 1
    film_gemm_fused<<<film_grid, 512, smem_film>>>(features, 0);
    aggregate_ln_kernel<<<agg_grid, 256>>>(g1, b1);

    // layer 2
    film_gemm_fused<<<film_grid, 512, smem_film>>>(nullptr, 1);
    aggregate_ln_kernel<<<agg_grid, 256>>>(g2, b2);

    // output head
    gemm_out_tc<<<(N_NODES + 63) / 64, 256, smem_out>>>(bp, out);
}

// round 4
// speedup vs baseline: 2.2112x; 1.2428x over previous
#include <cuda_runtime.h>

#define N_NODES 50000
#define N_EDGES 600000
#define DIM 128
#define OUTD 64

#define PADA 132   // words per row for A tiles (k-stride)
#define PADB 68    // words per row for B 64-k chunks

// ---- scratch (static device globals; no runtime allocation) ----
__device__ float    g_msg[N_NODES * DIM];
__device__ float    g_h[N_NODES * DIM];
__device__ int      g_deg[N_NODES];
__device__ int      g_off[N_NODES];
__device__ int      g_cur[N_NODES];
__device__ int      g_ctr;
__device__ int      g_csr_src[N_EDGES];
__device__ unsigned g_Bt1[2 * 192 * 128];   // layer-1 weights, tf32, usage order
__device__ unsigned g_Bt2[2 * 192 * 128];   // layer-2 weights
__device__ unsigned g_Bp[64 * 128];         // Wp, tf32

// ============================ helpers ============================

__device__ __forceinline__ unsigned f2tf32(float f) {
    unsigned u;
    asm("cvt.rna.tf32.f32 %0, %1;" : "=r"(u) : "f"(f));
    return u;
}

__device__ __forceinline__ void mma_tf32(float* c,
                                         unsigned a0, unsigned a1, unsigned a2, unsigned a3,
                                         unsigned b0, unsigned b1) {
    asm volatile(
        "mma.sync.aligned.m16n8k8.row.col.f32.tf32.tf32.f32 "
        "{%0,%1,%2,%3}, {%4,%5,%6,%7}, {%8,%9}, {%0,%1,%2,%3};"
        : "+f"(c[0]), "+f"(c[1]), "+f"(c[2]), "+f"(c[3])
        : "r"(a0), "r"(a1), "r"(a2), "r"(a3), "r"(b0), "r"(b1));
}

// ============================ CSR build ============================

__global__ void zero_deg_kernel() {
    int i = blockIdx.x * blockDim.x + threadIdx.x;
    if (i < N_NODES) g_deg[i] = 0;
    if (i == 0) g_ctr = 0;
}

__global__ void hist_kernel(const int* __restrict__ dst) {
    int e = blockIdx.x * blockDim.x + threadIdx.x;
    if (e < N_EDGES) atomicAdd(&g_deg[dst[e]], 1);
}

// unordered disjoint range claim (replaces ordered scan; aggregation is order-agnostic)
__global__ void offsets_kernel() {
    int i = blockIdx.x * blockDim.x + threadIdx.x;
    if (i < N_NODES) {
        int d = g_deg[i];
        int s = atomicAdd(&g_ctr, d);
        g_off[i] = s;
        g_cur[i] = s;
    }
}

__global__ void fill_csr_kernel(const int* __restrict__ src, const int* __restrict__ dst) {
    int e = blockIdx.x * blockDim.x + threadIdx.x;
    if (e < N_EDGES) {
        int d = dst[e];
        int p = atomicAdd(&g_cur[d], 1);
        g_csr_src[p] = src[e];
    }
}

// ==================== weight pre-conversion (fp32 -> tf32, usage order) ====================

__global__ void prep_weights(const float* __restrict__ W,
                             const float* __restrict__ F,
                             int layer) {
    unsigned* dst = layer ? g_Bt2 : g_Bt1;
    int idx = blockIdx.x * blockDim.x + threadIdx.x;   // over 2*192*32 float4 groups
    if (idx >= 2 * 192 * 32) return;
    int j  = idx / (192 * 32);
    int r  = (idx >> 5) % 192;
    int c4 = (idx & 31) * 4;
    const float* srcRow;
    if (r < 64)       srcRow = W + (64 * j + r) * 128;
    else if (r < 128) srcRow = F + (64 * j + r - 64) * 128;
    else              srcRow = F + (64 * j + r) * 128;
    float4 v = *(const float4*)(srcRow + c4);
    unsigned* p = dst + idx * 4;
    p[0] = f2tf32(v.x); p[1] = f2tf32(v.y); p[2] = f2tf32(v.z); p[3] = f2tf32(v.w);
}

__global__ void prep_wp(const float* __restrict__ Wp) {
    int idx = blockIdx.x * blockDim.x + threadIdx.x;   // over 64*32 float4 groups
    if (idx >= 64 * 32) return;
    float4 v = *(const float4*)(Wp + idx * 4);
    unsigned* p = g_Bp + idx * 4;
    p[0] = f2tf32(v.x); p[1] = f2tf32(v.y); p[2] = f2tf32(v.z); p[3] = f2tf32(v.w);
}

// ==================== fused FiLM GEMM (tf32 tensor cores, M=128, 512 thr) ====================

__global__ void film_gemm_fused(const float* __restrict__ Ain, int layer) {
    extern __shared__ unsigned smem[];
    unsigned* sA = smem;                   // 128*PADA
    unsigned* sB = smem + 128 * PADA;      // 192*PADB

    const float*    A  = layer ? g_h : Ain;
    const unsigned* Bt = layer ? g_Bt2 : g_Bt1;

    int tid  = threadIdx.x;     // 512
    int wid  = tid >> 5;
    int lane = tid & 31;
    int g    = lane >> 2;       // 0..7
    int tg   = lane & 3;        // 0..3
    int wr   = wid >> 1;        // 0..7 (16-row group)
    int wc   = wid & 1;         // 0..1 (32-col group)
    int row0 = blockIdx.x * 128;

    // load A tile (128 rows x 128 K) as tf32
    for (int idx = tid; idx < 128 * 32; idx += 512) {
        int r = idx >> 5;
        int c4 = (idx & 31) * 4;
        int grow = row0 + r;
        float4 v = (grow < N_NODES) ? *(const float4*)(A + grow * 128 + c4)
                                    : make_float4(0.f, 0.f, 0.f, 0.f);
        unsigned* p = sA + r * PADA + c4;
        p[0] = f2tf32(v.x); p[1] = f2tf32(v.y); p[2] = f2tf32(v.z); p[3] = f2tf32(v.w);
    }

#pragma unroll
    for (int j = 0; j < 2; j++) {
        float acc[3][4][4];
#pragma unroll
        for (int m = 0; m < 3; m++)
#pragma unroll
            for (int n = 0; n < 4; n++)
#pragma unroll
                for (int q = 0; q < 4; q++) acc[m][n][q] = 0.f;

#pragma unroll
        for (int kc = 0; kc < 2; kc++) {
            int kb = kc * 64;
            __syncthreads();
            // copy 192 weight rows x 64 K-chunk (already tf32)
            for (int idx = tid; idx < 192 * 16; idx += 512) {
                int r = idx >> 4;
                int c4 = (idx & 15) * 4;
                uint4 v = *(const uint4*)(Bt + (j * 192 + r) * 128 + kb + c4);
                *(uint4*)(sB + r * PADB + c4) = v;
            }
            __syncthreads();

            const unsigned* aW = sA + (wr * 16 + g) * PADA + kb + tg;
#pragma unroll
            for (int ks = 0; ks < 8; ks++) {
                int k0 = ks * 8;
                unsigned a0 = aW[k0];
                unsigned a1 = aW[8 * PADA + k0];
                unsigned a2 = aW[k0 + 4];
                unsigned a3 = aW[8 * PADA + k0 + 4];
#pragma unroll
                for (int mat = 0; mat < 3; mat++) {
#pragma unroll
                    for (int nt = 0; nt < 4; nt++) {
                        const unsigned* bptr = sB + (mat * 64 + wc * 32 + nt * 8 + g) * PADB + k0 + tg;
                        mma_tf32(acc[mat][nt], a0, a1, a2, a3, bptr[0], bptr[4]);
                    }
                }
            }
        }

        // epilogue: msg = relu(gamma*m + beta)
        int ra = row0 + wr * 16 + g;
        int rb = ra + 8;
#pragma unroll
        for (int nt = 0; nt < 4; nt++) {
            int col = 64 * j + wc * 32 + nt * 8 + 2 * tg;
            float v0 = fmaxf(fmaf(acc[1][nt][0], acc[0][nt][0], acc[2][nt][0]), 0.f);
            float v1 = fmaxf(fmaf(acc[1][nt][1], acc[0][nt][1], acc[2][nt][1]), 0.f);
            float v2 = fmaxf(fmaf(acc[1][nt][2], acc[0][nt][2], acc[2][nt][2]), 0.f);
            float v3 = fmaxf(fmaf(acc[1][nt][3], acc[0][nt][3], acc[2][nt][3]), 0.f);
            if (ra < N_NODES) *(float2*)&g_msg[ra * 128 + col] = make_float2(v0, v1);
            if (rb < N_NODES) *(float2*)&g_msg[rb * 128 + col] = make_float2(v2, v3);
        }
    }
}

// ==================== output head: sigmoid(g_h @ Wp.T + bp) ====================

__global__ void gemm_out_tc(const float* __restrict__ bp,
                            float* __restrict__ out) {
    extern __shared__ unsigned smem[];
    unsigned* sA = smem;                 // 64*PADA
    unsigned* sB = smem + 64 * PADA;     // 64*PADA

    int tid  = threadIdx.x;
    int wid  = tid >> 5;
    int lane = tid & 31;
    int g    = lane >> 2;
    int tg   = lane & 3;
    int wr   = wid >> 1;
    int wc   = wid & 1;
    int row0 = blockIdx.x * 64;

    for (int idx = tid; idx < 64 * 32; idx += 256) {
        int r = idx >> 5;
        int c4 = (idx & 31) * 4;
        int grow = row0 + r;
        float4 v = (grow < N_NODES) ? *(const float4*)(g_h + grow * 128 + c4)
                                    : make_float4(0.f, 0.f, 0.f, 0.f);
        unsigned* p = sA + r * PADA + c4;
        p[0] = f2tf32(v.x); p[1] = f2tf32(v.y); p[2] = f2tf32(v.z); p[3] = f2tf32(v.w);
    }
    for (int idx = tid; idx < 64 * 32; idx += 256) {
        int r = idx >> 5;
        int c4 = (idx & 31) * 4;
        uint4 v = *(const uint4*)(g_Bp + r * 128 + c4);
        *(uint4*)(sB + r * PADA + c4) = v;
    }
    __syncthreads();

    float acc[4][4];
#pragma unroll
    for (int n = 0; n < 4; n++)
#pragma unroll
        for (int q = 0; q < 4; q++) acc[n][q] = 0.f;

    const unsigned* aW = sA + (wr * 16 + g) * PADA + tg;
#pragma unroll
    for (int ks = 0; ks < 16; ks++) {
        int k0 = ks * 8;
        unsigned a0 = aW[k0];
        unsigned a1 = aW[8 * PADA + k0];
        unsigned a2 = aW[k0 + 4];
        unsigned a3 = aW[8 * PADA + k0 + 4];
#pragma unroll
        for (int nt = 0; nt < 4; nt++) {
            const unsigned* bptr = sB + (wc * 32 + nt * 8 + g) * PADA + k0 + tg;
            mma_tf32(acc[nt], a0, a1, a2, a3, bptr[0], bptr[4]);
        }
    }

    int ra = row0 + wr * 16 + g;
    int rb = ra + 8;
#pragma unroll
    for (int nt = 0; nt < 4; nt++) {
        int col = wc * 32 + nt * 8 + 2 * tg;
        float bpv0 = bp[col], bpv1 = bp[col + 1];
        float v0 = 1.f / (1.f + __expf(-(acc[nt][0] + bpv0)));
        float v1 = 1.f / (1.f + __expf(-(acc[nt][1] + bpv1)));
        float v2 = 1.f / (1.f + __expf(-(acc[nt][2] + bpv0)));
        float v3 = 1.f / (1.f + __expf(-(acc[nt][3] + bpv1)));
        if (ra < N_NODES) *(float2*)&out[ra * 64 + col] = make_float2(v0, v1);
        if (rb < N_NODES) *(float2*)&out[rb * 64 + col] = make_float2(v2, v3);
    }
}

// ==================== aggregate + layernorm (fused, warp per node) ====================

__global__ void aggregate_ln_kernel(const float* __restrict__ gam,
                                    const float* __restrict__ bet) {
    int gw = (blockIdx.x * blockDim.x + threadIdx.x) >> 5;
    int lane = threadIdx.x & 31;
    if (gw >= N_NODES) return;

    int s0 = g_off[gw], s1 = s0 + g_deg[gw];
    const float4* msg4 = (const float4*)g_msg;

    float4 acc0 = make_float4(0.f, 0.f, 0.f, 0.f);
    float4 acc1 = make_float4(0.f, 0.f, 0.f, 0.f);
    int i = s0;
    for (; i + 2 <= s1; i += 2) {
        int sa = __ldg(&g_csr_src[i]);
        int sb = __ldg(&g_csr_src[i + 1]);
        float4 va = __ldg(&msg4[sa * 32 + lane]);
        float4 vb = __ldg(&msg4[sb * 32 + lane]);
        acc0.x += va.x; acc0.y += va.y; acc0.z += va.z; acc0.w += va.w;
        acc1.x += vb.x; acc1.y += vb.y; acc1.z += vb.z; acc1.w += vb.w;
    }
    if (i < s1) {
        int sa = __ldg(&g_csr_src[i]);
        float4 va = __ldg(&msg4[sa * 32 + lane]);
        acc0.x += va.x; acc0.y += va.y; acc0.z += va.z; acc0.w += va.w;
    }
    float4 acc = make_float4(acc0.x + acc1.x, acc0.y + acc1.y,
                             acc0.z + acc1.z, acc0.w + acc1.w);

    float sum = acc.x + acc.y + acc.z + acc.w;
    float sq  = acc.x * acc.x + acc.y * acc.y + acc.z * acc.z + acc.w * acc.w;
#pragma unroll
    for (int o = 16; o > 0; o >>= 1) {
        sum += __shfl_xor_sync(0xffffffffu, sum, o);
        sq  += __shfl_xor_sync(0xffffffffu, sq,  o);
    }
    float mu  = sum * (1.f / 128.f);
    float var = sq * (1.f / 128.f) - mu * mu;
    float rs  = rsqrtf(var + 1e-5f);

    float4 gv = *(const float4*)&gam[lane * 4];
    float4 bv = *(const float4*)&bet[lane * 4];
    float4 o;
    o.x = (acc.x - mu) * rs * gv.x + bv.x;
    o.y = (acc.y - mu) * rs * gv.y + bv.y;
    o.z = (acc.z - mu) * rs * gv.z + bv.z;
    o.w = (acc.w - mu) * rs * gv.w + bv.w;
    *(float4*)&g_h[gw * 128 + lane * 4] = o;
}

// ============================ launch ============================

extern "C" void kernel_launch(void* const* d_in, const int* in_sizes, int n_in,
                              void* d_out, int out_size) {
    const float* features = (const float*)d_in[0];
    const int*   src      = (const int*)  d_in[1];
    const int*   dst      = (const int*)  d_in[2];
    const float* W1       = (const float*)d_in[3];
    const float* F1       = (const float*)d_in[4];
    const float* g1       = (const float*)d_in[5];
    const float* b1       = (const float*)d_in[6];
    const float* W2       = (const float*)d_in[7];
    const float* F2       = (const float*)d_in[8];
    const float* g2       = (const float*)d_in[9];
    const float* b2       = (const float*)d_in[10];
    const float* Wp       = (const float*)d_in[11];
    const float* bp       = (const float*)d_in[12];
    float* out = (float*)d_out;

    // persistent side stream + events (host resources, created once; the
    // captured work is identical on every call)
    static cudaStream_t s_side = nullptr;
    static cudaEvent_t  ev_fork = nullptr, ev_join = nullptr;
    if (s_side == nullptr) {
        cudaStreamCreateWithFlags(&s_side, cudaStreamNonBlocking);
        cudaEventCreateWithFlags(&ev_fork, cudaEventDisableTiming);
        cudaEventCreateWithFlags(&ev_join, cudaEventDisableTiming);
    }

    const int smem_film = (128 * PADA + 192 * PADB) * 4;   // 119808 B
    const int smem_out  = (64 * PADA + 64 * PADA) * 4;     // 67584 B
    cudaFuncSetAttribute(film_gemm_fused, cudaFuncAttributeMaxDynamicSharedMemorySize, smem_film);
    cudaFuncSetAttribute(gemm_out_tc,     cudaFuncAttributeMaxDynamicSharedMemorySize, smem_out);

    dim3 film_grid((N_NODES + 127) / 128);
    dim3 agg_grid((N_NODES + 7) / 8);

    // fork side branch off the capture-origin stream
    cudaEventRecord(ev_fork, 0);
    cudaStreamWaitEvent(s_side, ev_fork, 0);

    // branch B (side stream): CSR build + layer-2/head weight prep
    zero_deg_kernel<<<(N_NODES + 255) / 256, 256, 0, s_side>>>();
    hist_kernel<<<(N_EDGES + 255) / 256, 256, 0, s_side>>>(dst);
    offsets_kernel<<<(N_NODES + 255) / 256, 256, 0, s_side>>>();
    fill_csr_kernel<<<(N_EDGES + 255) / 256, 256, 0, s_side>>>(src, dst);
    prep_weights<<<(2 * 192 * 32 + 255) / 256, 256, 0, s_side>>>(W2, F2, 1);
    prep_wp<<<(64 * 32 + 255) / 256, 256, 0, s_side>>>(Wp);
    cudaEventRecord(ev_join, s_side);

    // branch A (origin stream): layer-1 prep + GEMM
    prep_weights<<<(2 * 192 * 32 + 255) / 256, 256>>>(W1, F1, 0);
    film_gemm_fused<<<film_grid, 512, smem_film>>>(features, 0);

    // join: aggregation needs CSR + msg
    cudaStreamWaitEvent(0, ev_join, 0);
    aggregate_ln_kernel<<<agg_grid, 256>>>(g1, b1);

    // layer 2
    film_gemm_fused<<<film_grid, 512, smem_film>>>(nullptr, 1);
    aggregate_ln_kernel<<<agg_grid, 256>>>(g2, b2);

    // output head
    gemm_out_tc<<<(N_NODES + 63) / 64, 256, smem_out>>>(bp, out);
}